// round 10
// baseline (speedup 1.0000x reference)
#include <cuda_runtime.h>
#include <cuda_bf16.h>
#include <cstdint>
#include <cstring>

// Problem dims
#define BDIM 16384
#define KDIM 4096
#define NDIM 512

// Binarized weight, bf16 {0,1}, [NDIM, KDIM] row-major (K-contiguous). 4 MB.
__device__ __align__(256) __nv_bfloat16 g_wbin[(size_t)NDIM * KDIM];

// ---------------------------------------------------------------------------
// helpers
// ---------------------------------------------------------------------------
__device__ __forceinline__ uint32_t smem_u32(const void* p) {
    uint32_t a;
    asm("{ .reg .u64 t; cvta.to.shared.u64 t, %1; cvt.u32.u64 %0, t; }"
        : "=r"(a) : "l"(p));
    return a;
}

#define SWZ(off) ((uint32_t)(off) ^ ((((uint32_t)(off)) >> 3) & 0x70))

#define LDSM_X4(r0, r1, r2, r3, addr) \
    asm volatile("ldmatrix.sync.aligned.m8n8.x4.shared.b16 {%0,%1,%2,%3}, [%4];" \
        : "=r"(r0), "=r"(r1), "=r"(r2), "=r"(r3) : "r"(addr))

#define MMA16816(d, a, b0, b1) \
    asm volatile("mma.sync.aligned.m16n8k16.row.col.f32.bf16.bf16.f32 " \
        "{%0,%1,%2,%3}, {%4,%5,%6,%7}, {%8,%9}, {%0,%1,%2,%3};" \
        : "+f"((d)[0]), "+f"((d)[1]), "+f"((d)[2]), "+f"((d)[3]) \
        : "r"((a)[0]), "r"((a)[1]), "r"((a)[2]), "r"((a)[3]), "r"(b0), "r"(b1))

#define STS128(addr, a, b, c, d) \
    asm volatile("st.shared.v4.b32 [%0], {%1, %2, %3, %4};" \
        :: "r"(addr), "r"(a), "r"(b), "r"(c), "r"(d) : "memory")

// named producer/consumer barriers (full: 1..4, empty: 5..8)
#define BAR_SYNC(id, cnt) \
    asm volatile("bar.sync %0, %1;" :: "r"(id), "r"(cnt) : "memory")
#define BAR_ARRIVE(id, cnt) \
    asm volatile("bar.arrive %0, %1;" :: "r"(id), "r"(cnt) : "memory")

__device__ __forceinline__ uint32_t pack_bf16x2(float lo, float hi) {
    __nv_bfloat162 h = __floats2bfloat162_rn(lo, hi);
    uint32_t r;
    memcpy(&r, &h, 4);
    return r;
}

// ---------------------------------------------------------------------------
// Kernel 1: binarize weight -> bf16 {0,1}. Pure bit select, no float math.
// ---------------------------------------------------------------------------
__global__ void __launch_bounds__(256) binarize_kernel(
    const float* __restrict__ w, const float* __restrict__ u) {
    int i = blockIdx.x * 256 + threadIdx.x;   // 8 elems each
    const float4* w4 = reinterpret_cast<const float4*>(w) + (size_t)i * 2;
    const float4* u4 = reinterpret_cast<const float4*>(u) + (size_t)i * 2;
    float4 wa = w4[0], wb = w4[1];
    float4 ua = u4[0], ub = u4[1];
    // bf16(1.0f) = 0x3F80
    uint32_t o0 = (ua.x < wa.x ? 0x00003F80u : 0u) | (ua.y < wa.y ? 0x3F800000u : 0u);
    uint32_t o1 = (ua.z < wa.z ? 0x00003F80u : 0u) | (ua.w < wa.w ? 0x3F800000u : 0u);
    uint32_t o2 = (ub.x < wb.x ? 0x00003F80u : 0u) | (ub.y < wb.y ? 0x3F800000u : 0u);
    uint32_t o3 = (ub.z < wb.z ? 0x00003F80u : 0u) | (ub.w < wb.w ? 0x3F800000u : 0u);
    reinterpret_cast<uint4*>(g_wbin)[i] = make_uint4(o0, o1, o2, o3);
}

// ---------------------------------------------------------------------------
// Kernel 2: warp-specialized bf16 GEMM with FUSED fp32->bf16 conversion.
//   out[16384, 512] = bf16(x) @ g_wbin^T
//   384 threads: warps 0-7 consumers (R9 layout: BM=128/BN=128, warp tile
//   32x64, pure ldmatrix+mma), warps 8-11 producers (LDG x fp32 -> cvt ->
//   STS bf16 A; LDG -> STS B). 4-stage ring, named-barrier handshake.
//   (R8 proved in-line fusion spills; producers keep reg alloc uniform ~120.
//    Deletes the 60us convert kernel + its 384MB DRAM round trip.)
// ---------------------------------------------------------------------------
static constexpr int BM = 128, BN = 128, BK = 64;
static constexpr int NC = KDIM / BK;              // 64
static constexpr int THREADS = 384;               // 8 consumer + 4 producer warps
static constexpr int STAGES = 4;

static constexpr int A_ST  = BM * 128;            // 16 KB
static constexpr int B_ST  = BN * 128;            // 16 KB
static constexpr int STAGE = A_ST + B_ST;         // 32 KB
static constexpr int SMEM_TOTAL = STAGES * STAGE; // 128 KB

__global__ void __launch_bounds__(THREADS, 1) binlin_gemm(
    const float* __restrict__ x, float* __restrict__ out) {
    extern __shared__ char smem[];
    const uint32_t smem_base = smem_u32(smem);
    const int tid = threadIdx.x;
    const int wid = tid >> 5;
    const int lid = tid & 31;

    const int n0 = blockIdx.x * BN;               // 0..384 step 128
    const int m0 = blockIdx.y * BM;               // 0..16256 step 128

    if (wid < 8) {
        // ================= CONSUMERS: ldmatrix + mma only =================
        const int warp_m = wid & 3;               // 0..3  (32 rows each)
        const int warp_n = wid >> 2;              // 0..1  (64 cols each)

        const int lr = lid & 7;
        const int lg = lid >> 3;
        const int a_row  = warp_m * 32 + (lg & 1) * 8 + lr;
        const int a_colb = (lg >> 1) * 16;
        const int b_row  = warp_n * 64 + (lg >> 1) * 8 + lr;
        const int b_colb = (lg & 1) * 16;

        float acc[2][8][4];
        #pragma unroll
        for (int i = 0; i < 2; i++)
            #pragma unroll
            for (int j = 0; j < 8; j++)
                #pragma unroll
                for (int k = 0; k < 4; k++) acc[i][j][k] = 0.f;

        int s = 0;
        for (int c = 0; c < NC; c++) {
            BAR_SYNC(1 + s, THREADS);             // wait stage s full
            const uint32_t abase = smem_base + s * STAGE;
            const uint32_t bbase = abase + A_ST;

            #pragma unroll
            for (int ks = 0; ks < 4; ks++) {
                uint32_t a[2][4];
                #pragma unroll
                for (int mf = 0; mf < 2; mf++) {
                    const uint32_t addr = abase +
                        SWZ((a_row + mf * 16) * 128 + ks * 32 + a_colb);
                    LDSM_X4(a[mf][0], a[mf][1], a[mf][2], a[mf][3], addr);
                }
                uint32_t b[4][4];
                #pragma unroll
                for (int nf2 = 0; nf2 < 4; nf2++) {
                    const uint32_t addr = bbase +
                        SWZ((b_row + nf2 * 16) * 128 + ks * 32 + b_colb);
                    LDSM_X4(b[nf2][0], b[nf2][1], b[nf2][2], b[nf2][3], addr);
                }
                #pragma unroll
                for (int mf = 0; mf < 2; mf++) {
                    #pragma unroll
                    for (int nf = 0; nf < 8; nf++) {
                        MMA16816(acc[mf][nf], a[mf],
                                 b[nf >> 1][(nf & 1) * 2 + 0],
                                 b[nf >> 1][(nf & 1) * 2 + 1]);
                    }
                }
            }

            if (c + STAGES < NC)
                BAR_ARRIVE(5 + s, THREADS);       // stage s free for c+4
            if (++s == STAGES) s = 0;
        }

        // ---- epilogue ----
        const int er = lid >> 2;
        const int ec = (lid & 3) * 2;
        #pragma unroll
        for (int mf = 0; mf < 2; mf++) {
            #pragma unroll
            for (int nf = 0; nf < 8; nf++) {
                const int m = m0 + warp_m * 32 + mf * 16 + er;
                const int n = n0 + warp_n * 64 + nf * 8 + ec;
                float2 v0 = make_float2(acc[mf][nf][0], acc[mf][nf][1]);
                float2 v1 = make_float2(acc[mf][nf][2], acc[mf][nf][3]);
                *reinterpret_cast<float2*>(out + (size_t)m * NDIM + n)       = v0;
                *reinterpret_cast<float2*>(out + (size_t)(m + 8) * NDIM + n) = v1;
            }
        }
    } else {
        // ================= PRODUCERS: gmem -> smem =================
        const int p = tid - 256;                  // 0..127
        const int r = p >> 3;                     // base row step 16 (task = p + j*128)
        const int t = p & 7;                      // 16B segment
        const float*         ax = x      + (size_t)m0 * KDIM;
        const __nv_bfloat16* bw = g_wbin + (size_t)n0 * KDIM;

        int s = 0;
        for (int c = 0; c < NC; c++) {
            if (c >= STAGES) BAR_SYNC(5 + s, THREADS);   // wait stage s empty

            const uint32_t abase = smem_base + s * STAGE;
            const uint32_t bbase = abase + A_ST;
            const float*         asrc = ax + (size_t)c * BK;
            const __nv_bfloat16* bsrc = bw + (size_t)c * BK;

            // issue all loads first (max MLP)
            float4 av0[8], av1[8];
            #pragma unroll
            for (int j = 0; j < 8; j++) {
                const int rr = r + j * 16;
                const float4* q = reinterpret_cast<const float4*>(
                    asrc + (size_t)rr * KDIM + t * 8);
                av0[j] = q[0];
                av1[j] = q[1];
            }
            uint4 bv[8];
            #pragma unroll
            for (int j = 0; j < 8; j++) {
                const int rr = r + j * 16;
                bv[j] = *reinterpret_cast<const uint4*>(
                    bsrc + (size_t)rr * KDIM + t * 8);
            }
            // convert + store A
            #pragma unroll
            for (int j = 0; j < 8; j++) {
                const int rr = r + j * 16;
                uint32_t u0 = pack_bf16x2(av0[j].x, av0[j].y);
                uint32_t u1 = pack_bf16x2(av0[j].z, av0[j].w);
                uint32_t u2 = pack_bf16x2(av1[j].x, av1[j].y);
                uint32_t u3 = pack_bf16x2(av1[j].z, av1[j].w);
                STS128(abase + SWZ(rr * 128 + t * 16), u0, u1, u2, u3);
            }
            // store B
            #pragma unroll
            for (int j = 0; j < 8; j++) {
                const int rr = r + j * 16;
                STS128(bbase + SWZ(rr * 128 + t * 16),
                       bv[j].x, bv[j].y, bv[j].z, bv[j].w);
            }

            BAR_ARRIVE(1 + s, THREADS);           // stage s full
            if (++s == STAGES) s = 0;
        }
    }
}

// ---------------------------------------------------------------------------
// Launch
// ---------------------------------------------------------------------------
extern "C" void kernel_launch(void* const* d_in, const int* in_sizes, int n_in,
                              void* d_out, int out_size) {
    const float* x = (const float*)d_in[0];   // [16384, 4096]
    const float* w = (const float*)d_in[1];   // [512, 4096] bernoulli probs
    const float* u = (const float*)d_in[2];   // [512, 4096] uniform sample
    float* out = (float*)d_out;               // [16384, 512]

    cudaFuncSetAttribute(binlin_gemm,
                         cudaFuncAttributeMaxDynamicSharedMemorySize, SMEM_TOTAL);

    binarize_kernel<<<(NDIM * KDIM) / (256 * 8), 256>>>(w, u);
    dim3 grid(NDIM / BN, BDIM / BM);          // (4, 128) = 512 CTAs
    binlin_gemm<<<grid, THREADS, SMEM_TOTAL>>>(x, out);
}

// round 11
// speedup vs baseline: 1.3167x; 1.3167x over previous
#include <cuda_runtime.h>
#include <cuda_bf16.h>
#include <cstdint>
#include <cstring>

// Problem dims
#define BDIM 16384
#define KDIM 4096
#define NDIM 512

// Binarized weight, bf16 {0,1}, [NDIM, KDIM] row-major (K-contiguous). 4 MB.
__device__ __align__(256) __nv_bfloat16 g_wbin[(size_t)NDIM * KDIM];

// ---------------------------------------------------------------------------
// helpers
// ---------------------------------------------------------------------------
__device__ __forceinline__ uint32_t smem_u32(const void* p) {
    uint32_t a;
    asm("{ .reg .u64 t; cvta.to.shared.u64 t, %1; cvt.u32.u64 %0, t; }"
        : "=r"(a) : "l"(p));
    return a;
}

#define SWZ(off) ((uint32_t)(off) ^ ((((uint32_t)(off)) >> 3) & 0x70))

#define LDSM_X4(r0, r1, r2, r3, addr) \
    asm volatile("ldmatrix.sync.aligned.m8n8.x4.shared.b16 {%0,%1,%2,%3}, [%4];" \
        : "=r"(r0), "=r"(r1), "=r"(r2), "=r"(r3) : "r"(addr))

#define MMA16816(d, a, b0, b1) \
    asm volatile("mma.sync.aligned.m16n8k16.row.col.f32.bf16.bf16.f32 " \
        "{%0,%1,%2,%3}, {%4,%5,%6,%7}, {%8,%9}, {%0,%1,%2,%3};" \
        : "+f"((d)[0]), "+f"((d)[1]), "+f"((d)[2]), "+f"((d)[3]) \
        : "r"((a)[0]), "r"((a)[1]), "r"((a)[2]), "r"((a)[3]), "r"(b0), "r"(b1))

#define CP_ASYNC16(dst, src) \
    asm volatile("cp.async.cg.shared.global [%0], [%1], 16;" \
        :: "r"(dst), "l"(src) : "memory")
#define CP_COMMIT() asm volatile("cp.async.commit_group;" ::: "memory")
#define CP_WAIT2()  asm volatile("cp.async.wait_group 2;" ::: "memory")

#define STS128(addr, a, b, c, d) \
    asm volatile("st.shared.v4.b32 [%0], {%1, %2, %3, %4};" \
        :: "r"(addr), "r"(a), "r"(b), "r"(c), "r"(d) : "memory")

// named producer/consumer barriers (A-stage full: 1..4, A-stage empty: 5..8)
#define BAR_SYNC(id, cnt) \
    asm volatile("bar.sync %0, %1;" :: "r"(id), "r"(cnt) : "memory")
#define BAR_ARRIVE(id, cnt) \
    asm volatile("bar.arrive %0, %1;" :: "r"(id), "r"(cnt) : "memory")

__device__ __forceinline__ uint32_t pack_bf16x2(float lo, float hi) {
    __nv_bfloat162 h = __floats2bfloat162_rn(lo, hi);
    uint32_t r;
    memcpy(&r, &h, 4);
    return r;
}

// ---------------------------------------------------------------------------
// Kernel 1: binarize weight -> bf16 {0,1}. Pure bit select, no float math.
// ---------------------------------------------------------------------------
__global__ void __launch_bounds__(256) binarize_kernel(
    const float* __restrict__ w, const float* __restrict__ u) {
    int i = blockIdx.x * 256 + threadIdx.x;   // 8 elems each
    const float4* w4 = reinterpret_cast<const float4*>(w) + (size_t)i * 2;
    const float4* u4 = reinterpret_cast<const float4*>(u) + (size_t)i * 2;
    float4 wa = w4[0], wb = w4[1];
    float4 ua = u4[0], ub = u4[1];
    // bf16(1.0f) = 0x3F80
    uint32_t o0 = (ua.x < wa.x ? 0x00003F80u : 0u) | (ua.y < wa.y ? 0x3F800000u : 0u);
    uint32_t o1 = (ua.z < wa.z ? 0x00003F80u : 0u) | (ua.w < wa.w ? 0x3F800000u : 0u);
    uint32_t o2 = (ub.x < wb.x ? 0x00003F80u : 0u) | (ub.y < wb.y ? 0x3F800000u : 0u);
    uint32_t o3 = (ub.z < wb.z ? 0x00003F80u : 0u) | (ub.w < wb.w ? 0x3F800000u : 0u);
    reinterpret_cast<uint4*>(g_wbin)[i] = make_uint4(o0, o1, o2, o3);
}

// ---------------------------------------------------------------------------
// Kernel 2: warp-specialized bf16 GEMM with FUSED fp32->bf16 conversion.
//   out[16384, 512] = bf16(x) @ g_wbin^T
//   384 threads: warps 0-7 consumers (BM=128/BN=128, warp tile 32x64,
//   ldmatrix+mma + consumer-side cp.async for B), warps 8-11 producers
//   (A path: LDG x fp32 -> cvt -> STS bf16, PIPELINED one chunk ahead:
//    STS A(c) waits on LDG issued a full chunk earlier -> no exposed
//    latency; this was R10's failure mode).
//   A: 4-stage named-barrier ring. B: 4-stage consumer cp.async ring
//   (R4-proven). Deletes the 60us convert kernel + 384MB DRAM round trip.
// ---------------------------------------------------------------------------
static constexpr int BM = 128, BN = 128, BK = 64;
static constexpr int NC = KDIM / BK;              // 64
static constexpr int THREADS = 384;               // 8 consumer + 4 producer warps
static constexpr int STAGES = 4;

static constexpr int A_ST  = BM * 128;            // 16 KB
static constexpr int B_ST  = BN * 128;            // 16 KB
static constexpr int B_OFF = STAGES * A_ST;       // 64 KB
static constexpr int SMEM_TOTAL = B_OFF + STAGES * B_ST;  // 128 KB

__global__ void __launch_bounds__(THREADS, 1) binlin_gemm(
    const float* __restrict__ x, float* __restrict__ out) {
    extern __shared__ char smem[];
    const uint32_t smem_base = smem_u32(smem);
    const int tid = threadIdx.x;
    const int wid = tid >> 5;
    const int lid = tid & 31;

    const int n0 = blockIdx.x * BN;               // 0..384 step 128
    const int m0 = blockIdx.y * BM;               // 0..16256 step 128

    if (wid < 8) {
        // ========== CONSUMERS: ldmatrix + mma + B cp.async ==========
        const int warp_m = wid & 3;               // 0..3  (32 rows each)
        const int warp_n = wid >> 2;              // 0..1  (64 cols each)

        const int lr = lid & 7;
        const int lg = lid >> 3;
        const int a_row  = warp_m * 32 + (lg & 1) * 8 + lr;
        const int a_colb = (lg >> 1) * 16;
        const int b_row  = warp_n * 64 + (lg >> 1) * 8 + lr;
        const int b_colb = (lg & 1) * 16;

        // B staging coords (1024 16B tasks / 256 consumer threads = 4 each)
        const int br = tid >> 3;                  // row base (+ it*32)
        const int bt = tid & 7;                   // 16B segment
        const __nv_bfloat16* bw = g_wbin + (size_t)(n0 + 0) * KDIM;

        float acc[2][8][4];
        #pragma unroll
        for (int i = 0; i < 2; i++)
            #pragma unroll
            for (int j = 0; j < 8; j++)
                #pragma unroll
                for (int k = 0; k < 4; k++) acc[i][j][k] = 0.f;

        // B prologue: stages 0..2
        #pragma unroll
        for (int s = 0; s < 3; s++) {
            const __nv_bfloat16* bsrc = bw + (size_t)s * BK;
            const uint32_t bb = smem_base + B_OFF + s * B_ST;
            #pragma unroll
            for (int it = 0; it < 4; it++) {
                const int rr = br + it * 32;
                CP_ASYNC16(bb + SWZ(rr * 128 + bt * 16),
                           bsrc + (size_t)rr * KDIM + bt * 8);
            }
            CP_COMMIT();
        }

        int s = 0;
        for (int c = 0; c < NC; c++) {
            BAR_SYNC(1 + s, THREADS);             // A(c) ready; consumers aligned
            CP_WAIT2();                           // B(c) landed (3 pending -> oldest)

            // issue B(c+3): stage (c+3)&3 == (c-1)&3; all consumers are past
            // chunk c-1's reads (guaranteed by the full-A sync above).
            if (c + 3 < NC) {
                const __nv_bfloat16* bsrc = bw + (size_t)(c + 3) * BK;
                const uint32_t bb = smem_base + B_OFF + ((c + 3) & 3) * B_ST;
                #pragma unroll
                for (int it = 0; it < 4; it++) {
                    const int rr = br + it * 32;
                    CP_ASYNC16(bb + SWZ(rr * 128 + bt * 16),
                               bsrc + (size_t)rr * KDIM + bt * 8);
                }
            }
            CP_COMMIT();                          // lockstep (may be empty)

            const uint32_t abase = smem_base + s * A_ST;
            const uint32_t bbase = smem_base + B_OFF + (c & 3) * B_ST;

            #pragma unroll
            for (int ks = 0; ks < 4; ks++) {
                uint32_t a[2][4];
                #pragma unroll
                for (int mf = 0; mf < 2; mf++) {
                    const uint32_t addr = abase +
                        SWZ((a_row + mf * 16) * 128 + ks * 32 + a_colb);
                    LDSM_X4(a[mf][0], a[mf][1], a[mf][2], a[mf][3], addr);
                }
                uint32_t b[4][4];
                #pragma unroll
                for (int nf2 = 0; nf2 < 4; nf2++) {
                    const uint32_t addr = bbase +
                        SWZ((b_row + nf2 * 16) * 128 + ks * 32 + b_colb);
                    LDSM_X4(b[nf2][0], b[nf2][1], b[nf2][2], b[nf2][3], addr);
                }
                #pragma unroll
                for (int mf = 0; mf < 2; mf++) {
                    #pragma unroll
                    for (int nf = 0; nf < 8; nf++) {
                        MMA16816(acc[mf][nf], a[mf],
                                 b[nf >> 1][(nf & 1) * 2 + 0],
                                 b[nf >> 1][(nf & 1) * 2 + 1]);
                    }
                }
            }

            BAR_ARRIVE(5 + s, THREADS);           // A stage s free
            if (++s == STAGES) s = 0;
        }

        // ---- epilogue ----
        const int er = lid >> 2;
        const int ec = (lid & 3) * 2;
        #pragma unroll
        for (int mf = 0; mf < 2; mf++) {
            #pragma unroll
            for (int nf = 0; nf < 8; nf++) {
                const int m = m0 + warp_m * 32 + mf * 16 + er;
                const int n = n0 + warp_n * 64 + nf * 8 + ec;
                float2 v0 = make_float2(acc[mf][nf][0], acc[mf][nf][1]);
                float2 v1 = make_float2(acc[mf][nf][2], acc[mf][nf][3]);
                *reinterpret_cast<float2*>(out + (size_t)m * NDIM + n)       = v0;
                *reinterpret_cast<float2*>(out + (size_t)(m + 8) * NDIM + n) = v1;
            }
        }
    } else {
        // ========== PRODUCERS: x fp32 -> bf16 -> smem, pipelined ==========
        const int p = tid - 256;                  // 0..127
        const int rbase = p >> 3;                 // row base (+ j*16)
        const int t2 = p & 7;                     // 32B fp32 seg == 16B bf16 seg
        const float* ax = x + (size_t)m0 * KDIM;

        float4 buf[8][2];                         // one chunk: 8 rows x 8 fp32

        // prologue: LDG A(0)
        {
            const float* asrc = ax;               // chunk 0
            #pragma unroll
            for (int j = 0; j < 8; j++) {
                const int rr = rbase + j * 16;
                const float4* q = reinterpret_cast<const float4*>(
                    asrc + (size_t)rr * KDIM + t2 * 8);
                buf[j][0] = q[0];
                buf[j][1] = q[1];
            }
        }

        int s = 0;
        for (int c = 0; c < NC; c++) {
            if (c >= STAGES) BAR_SYNC(5 + s, THREADS);   // wait A stage s empty

            // STS A(c): scoreboard-waits on LDG issued a full chunk ago
            const uint32_t abase = smem_base + s * A_ST;
            #pragma unroll
            for (int j = 0; j < 8; j++) {
                const int rr = rbase + j * 16;
                uint32_t u0 = pack_bf16x2(buf[j][0].x, buf[j][0].y);
                uint32_t u1 = pack_bf16x2(buf[j][0].z, buf[j][0].w);
                uint32_t u2 = pack_bf16x2(buf[j][1].x, buf[j][1].y);
                uint32_t u3 = pack_bf16x2(buf[j][1].z, buf[j][1].w);
                STS128(abase + SWZ(rr * 128 + t2 * 16), u0, u1, u2, u3);
            }
            BAR_ARRIVE(1 + s, THREADS);           // A(c) full

            // LDG A(c+1) into the same buffer (WAR on regs resolved at issue;
            // completion lands long before next iteration's STS).
            if (c + 1 < NC) {
                const float* asrc = ax + (size_t)(c + 1) * BK;
                #pragma unroll
                for (int j = 0; j < 8; j++) {
                    const int rr = rbase + j * 16;
                    const float4* q = reinterpret_cast<const float4*>(
                        asrc + (size_t)rr * KDIM + t2 * 8);
                    buf[j][0] = q[0];
                    buf[j][1] = q[1];
                }
            }
            if (++s == STAGES) s = 0;
        }
    }
}

// ---------------------------------------------------------------------------
// Launch
// ---------------------------------------------------------------------------
extern "C" void kernel_launch(void* const* d_in, const int* in_sizes, int n_in,
                              void* d_out, int out_size) {
    const float* x = (const float*)d_in[0];   // [16384, 4096]
    const float* w = (const float*)d_in[1];   // [512, 4096] bernoulli probs
    const float* u = (const float*)d_in[2];   // [512, 4096] uniform sample
    float* out = (float*)d_out;               // [16384, 512]

    cudaFuncSetAttribute(binlin_gemm,
                         cudaFuncAttributeMaxDynamicSharedMemorySize, SMEM_TOTAL);

    binarize_kernel<<<(NDIM * KDIM) / (256 * 8), 256>>>(w, u);
    dim3 grid(NDIM / BN, BDIM / BM);          // (4, 128) = 512 CTAs
    binlin_gemm<<<grid, THREADS, SMEM_TOTAL>>>(x, out);
}